// round 2
// baseline (speedup 1.0000x reference)
#include <cuda_runtime.h>
#include <math.h>

// ---------------------------------------------------------------------------
// Problem constants (shapes fixed by dataset; runtime loop bounds come from
// in_sizes, static scratch sized to the max).
// ---------------------------------------------------------------------------
#define NW_MAX 100000
#define NS_MAX 25000
#define E_MAX  1600000

// ---------------------------------------------------------------------------
// Scratch (allocation-free rule: __device__ globals)
// ---------------------------------------------------------------------------
__device__ float g_Wmat[128 * 128];          // [i][h*16+d]
__device__ float g_vsrc[128 * 8];            // [i][h]
__device__ float g_vdst[128 * 8];            // [i][h]
__device__ float g_zw[(size_t)NW_MAX * 128]; // projected word feats
__device__ float g_esrc[NW_MAX * 8];
__device__ float g_edst[NS_MAX * 8];
__device__ int   g_cnt[NS_MAX];
__device__ int   g_off[NS_MAX + 1];
__device__ int   g_cur[NS_MAX];
__device__ int   g_csr[E_MAX];               // src indices bucketed by dst
__device__ float g_hbuf[NS_MAX * 128];       // elu(out)+s (pre-LN residual)
__device__ float g_xn[NS_MAX * 128];         // layernormed
__device__ float g_inter[(size_t)NS_MAX * 512];

__device__ __forceinline__ float gelu_exact(float x) {
    return 0.5f * x * (1.0f + erff(x * 0.70710678118654752f));
}

// ---------------------------------------------------------------------------
// Prep: Wmat[i][h*16+d] = Wfc[h,i,d]; v_src/v_dst[i][h] = sum_d Wfc[h,i,d]*a[h,d]
// ---------------------------------------------------------------------------
__global__ void prep_kernel(const float* __restrict__ Wfc,
                            const float* __restrict__ a_src,
                            const float* __restrict__ a_dst) {
    int idx = blockIdx.x * blockDim.x + threadIdx.x;
    if (idx < 128 * 128) {
        int i = idx >> 7;
        int hd = idx & 127;
        int h = hd >> 4, d = hd & 15;
        g_Wmat[i * 128 + hd] = Wfc[h * 2048 + i * 16 + d];
    }
    if (idx < 128 * 8) {
        int i = idx >> 3;
        int h = idx & 7;
        float s1 = 0.f, s2 = 0.f;
#pragma unroll
        for (int d = 0; d < 16; d++) {
            float wv = Wfc[h * 2048 + i * 16 + d];
            s1 = fmaf(wv, a_src[h * 16 + d], s1);
            s2 = fmaf(wv, a_dst[h * 16 + d], s2);
        }
        g_vsrc[i * 8 + h] = s1;
        g_vdst[i * 8 + h] = s2;
    }
}

// ---------------------------------------------------------------------------
// Tiled fp32 SGEMM: C[M,N] = act(A[M,K] @ B[K,N] + bias) + res
// 128x128 block tile, BK=8, 256 threads, 8x8 per-thread microtile.
// N must be a multiple of 128, K a multiple of 8.
// ---------------------------------------------------------------------------
template <bool GELU, bool BIAS, bool RES>
__global__ __launch_bounds__(256) void sgemm_kernel(
    const float* __restrict__ A, const float* __restrict__ B,
    const float* __restrict__ bias, const float* __restrict__ res,
    float* __restrict__ C, int M, int N, int K) {
    __shared__ float As[8][128];
    __shared__ float Bs[8][128];
    const int tid = threadIdx.x;
    const int tx = tid & 15;        // 16 col groups
    const int ty = tid >> 4;        // 16 row groups
    const int rowBase = blockIdx.y * 128;
    const int colBase = blockIdx.x * 128;

    float acc[8][8];
#pragma unroll
    for (int i = 0; i < 8; i++)
#pragma unroll
        for (int j = 0; j < 8; j++) acc[i][j] = 0.f;

    const int arow = tid >> 1, acol = (tid & 1) << 2;   // A: 128 rows x 8 k
    const int brow = tid >> 5, bcol = (tid & 31) << 2;  // B: 8 k x 128 cols
    const bool aval = (rowBase + arow) < M;
    const float* Aptr = A + (size_t)(rowBase + arow) * K + acol;
    const float* Bptr = B + (size_t)brow * N + colBase + bcol;

    for (int k0 = 0; k0 < K; k0 += 8) {
        float4 av = aval ? *(const float4*)(Aptr + k0)
                         : make_float4(0.f, 0.f, 0.f, 0.f);
        float4 bv = *(const float4*)(Bptr + (size_t)k0 * N);
        As[acol + 0][arow] = av.x;
        As[acol + 1][arow] = av.y;
        As[acol + 2][arow] = av.z;
        As[acol + 3][arow] = av.w;
        *(float4*)&Bs[brow][bcol] = bv;
        __syncthreads();
#pragma unroll
        for (int kk = 0; kk < 8; kk++) {
            float4 a0 = *(const float4*)&As[kk][ty * 8];
            float4 a1 = *(const float4*)&As[kk][ty * 8 + 4];
            float4 b0 = *(const float4*)&Bs[kk][tx * 8];
            float4 b1 = *(const float4*)&Bs[kk][tx * 8 + 4];
            float ar[8] = {a0.x, a0.y, a0.z, a0.w, a1.x, a1.y, a1.z, a1.w};
            float br[8] = {b0.x, b0.y, b0.z, b0.w, b1.x, b1.y, b1.z, b1.w};
#pragma unroll
            for (int i = 0; i < 8; i++)
#pragma unroll
                for (int j = 0; j < 8; j++)
                    acc[i][j] = fmaf(ar[i], br[j], acc[i][j]);
        }
        __syncthreads();
    }

#pragma unroll
    for (int i = 0; i < 8; i++) {
        int row = rowBase + ty * 8 + i;
        if (row >= M) continue;
#pragma unroll
        for (int j4 = 0; j4 < 8; j4 += 4) {
            int col = colBase + tx * 8 + j4;
            float v0 = acc[i][j4 + 0], v1 = acc[i][j4 + 1];
            float v2 = acc[i][j4 + 2], v3 = acc[i][j4 + 3];
            if (BIAS) {
                float4 bb = *(const float4*)(bias + col);
                v0 += bb.x; v1 += bb.y; v2 += bb.z; v3 += bb.w;
            }
            if (GELU) {
                v0 = gelu_exact(v0); v1 = gelu_exact(v1);
                v2 = gelu_exact(v2); v3 = gelu_exact(v3);
            }
            if (RES) {
                float4 rr = *(const float4*)(res + (size_t)row * N + col);
                v0 += rr.x; v1 += rr.y; v2 += rr.z; v3 += rr.w;
            }
            float4 ov = make_float4(v0, v1, v2, v3);
            *(float4*)(C + (size_t)row * N + col) = ov;
        }
    }
}

// ---------------------------------------------------------------------------
// e = X @ vmat  (X:[n,128], vmat:[128,8]) — one warp per row.
// ---------------------------------------------------------------------------
__global__ void proj_e_kernel(const float* __restrict__ X,
                              const float* __restrict__ vmat,
                              float* __restrict__ out, int n) {
    int warp = (blockIdx.x * blockDim.x + threadIdx.x) >> 5;
    if (warp >= n) return;
    int lane = threadIdx.x & 31;
    float4 xv = *(const float4*)(X + (size_t)warp * 128 + lane * 4);
    float acc[8];
#pragma unroll
    for (int h = 0; h < 8; h++) {
        acc[h] = xv.x * vmat[(lane * 4 + 0) * 8 + h]
               + xv.y * vmat[(lane * 4 + 1) * 8 + h]
               + xv.z * vmat[(lane * 4 + 2) * 8 + h]
               + xv.w * vmat[(lane * 4 + 3) * 8 + h];
    }
#pragma unroll
    for (int off = 16; off; off >>= 1)
#pragma unroll
        for (int h = 0; h < 8; h++)
            acc[h] += __shfl_xor_sync(0xffffffffu, acc[h], off);
    if (lane < 8) out[warp * 8 + lane] = acc[lane];
}

// ---------------------------------------------------------------------------
// CSR build
// ---------------------------------------------------------------------------
__global__ void zero_cnt_kernel(int ns) {
    int i = blockIdx.x * blockDim.x + threadIdx.x;
    if (i < ns) g_cnt[i] = 0;
}

__global__ void hist_kernel(const int* __restrict__ edst, int E) {
    for (int e = blockIdx.x * blockDim.x + threadIdx.x; e < E;
         e += gridDim.x * blockDim.x)
        atomicAdd(&g_cnt[edst[e]], 1);
}

__global__ void scan_kernel(int ns) {
    __shared__ int ssum[1024];
    int t = threadIdx.x;
    int per = (ns + 1023) >> 10;
    int base = t * per;
    int sum = 0;
    for (int i = 0; i < per; i++) {
        int idx = base + i;
        if (idx < ns) sum += g_cnt[idx];
    }
    ssum[t] = sum;
    __syncthreads();
    for (int off = 1; off < 1024; off <<= 1) {
        int v = (t >= off) ? ssum[t - off] : 0;
        __syncthreads();
        ssum[t] += v;
        __syncthreads();
    }
    int run = (t == 0) ? 0 : ssum[t - 1];
    for (int i = 0; i < per; i++) {
        int idx = base + i;
        if (idx < ns) {
            g_off[idx] = run;
            g_cur[idx] = run;
            run += g_cnt[idx];
        }
    }
    if (t == 1023) g_off[ns] = ssum[1023];
}

__global__ void scatter_kernel(const int* __restrict__ esrc_idx,
                               const int* __restrict__ edst_idx, int E) {
    for (int e = blockIdx.x * blockDim.x + threadIdx.x; e < E;
         e += gridDim.x * blockDim.x) {
        int dst = edst_idx[e];
        int pos = atomicAdd(&g_cur[dst], 1);
        g_csr[pos] = esrc_idx[e];
    }
}

// ---------------------------------------------------------------------------
// Aggregation: one warp per dst node. Two-pass segment softmax, registers
// only, no output atomics. Lane l owns output cols [4l,4l+4) (head = l/4).
// hbuf = elu(softmax-weighted sum) + s
// ---------------------------------------------------------------------------
__global__ void agg_kernel(const float* __restrict__ s, int ns) {
    int dst = (blockIdx.x * blockDim.x + threadIdx.x) >> 5;
    if (dst >= ns) return;
    int lane = threadIdx.x & 31;
    int h = lane >> 2;
    float ed = g_edst[dst * 8 + h];
    int beg = g_off[dst], end = g_off[dst + 1];

    // pass 1: per-head segment max of leaky_relu scores
    float m = -1e30f;
    for (int e = beg; e < end; ++e) {
        int src = g_csr[e];
        float sc = g_esrc[src * 8 + h] + ed;
        sc = sc > 0.f ? sc : 0.01f * sc;
        m = fmaxf(m, sc);
    }

    // pass 2: exp-weighted accumulate
    float d = 0.f;
    float ax = 0.f, ay = 0.f, az = 0.f, aw = 0.f;
    for (int e = beg; e < end; ++e) {
        int src = g_csr[e];
        float sc = g_esrc[src * 8 + h] + ed;
        sc = sc > 0.f ? sc : 0.01f * sc;
        float p = __expf(sc - m);
        d += p;
        float4 z = *(const float4*)(g_zw + (size_t)src * 128 + lane * 4);
        ax = fmaf(p, z.x, ax);
        ay = fmaf(p, z.y, ay);
        az = fmaf(p, z.z, az);
        aw = fmaf(p, z.w, aw);
    }
    float inv = 1.f / fmaxf(d, 1e-9f);
    float4 sv = *(const float4*)(s + (size_t)dst * 128 + lane * 4);
    float o0 = ax * inv, o1 = ay * inv, o2 = az * inv, o3 = aw * inv;
    o0 = o0 > 0.f ? o0 : (__expf(o0) - 1.f);
    o1 = o1 > 0.f ? o1 : (__expf(o1) - 1.f);
    o2 = o2 > 0.f ? o2 : (__expf(o2) - 1.f);
    o3 = o3 > 0.f ? o3 : (__expf(o3) - 1.f);
    float4 ov = make_float4(o0 + sv.x, o1 + sv.y, o2 + sv.z, o3 + sv.w);
    *(float4*)(g_hbuf + (size_t)dst * 128 + lane * 4) = ov;
}

// ---------------------------------------------------------------------------
// LayerNorm: one warp per row, population variance, eps=1e-6
// ---------------------------------------------------------------------------
__global__ void ln_kernel(const float* __restrict__ gamma,
                          const float* __restrict__ beta, int ns) {
    int row = (blockIdx.x * blockDim.x + threadIdx.x) >> 5;
    if (row >= ns) return;
    int lane = threadIdx.x & 31;
    float4 v = *(const float4*)(g_hbuf + (size_t)row * 128 + lane * 4);
    float sum = v.x + v.y + v.z + v.w;
    float sq = v.x * v.x + v.y * v.y + v.z * v.z + v.w * v.w;
#pragma unroll
    for (int o = 16; o; o >>= 1) {
        sum += __shfl_xor_sync(0xffffffffu, sum, o);
        sq += __shfl_xor_sync(0xffffffffu, sq, o);
    }
    float mean = sum * (1.f / 128.f);
    float var = sq * (1.f / 128.f) - mean * mean;
    float inv = rsqrtf(var + 1e-6f);
    float4 g = *(const float4*)(gamma + lane * 4);
    float4 b = *(const float4*)(beta + lane * 4);
    float4 o4;
    o4.x = (v.x - mean) * inv * g.x + b.x;
    o4.y = (v.y - mean) * inv * g.y + b.y;
    o4.z = (v.z - mean) * inv * g.z + b.z;
    o4.w = (v.w - mean) * inv * g.w + b.w;
    *(float4*)(g_xn + (size_t)row * 128 + lane * 4) = o4;
}

// ---------------------------------------------------------------------------
// Host launcher
// ---------------------------------------------------------------------------
template <typename T>
static T* sym_addr(const void* symbol) {
    void* p = nullptr;
    cudaGetSymbolAddress(&p, symbol);
    return (T*)p;
}

extern "C" void kernel_launch(void* const* d_in, const int* in_sizes, int n_in,
                              void* d_out, int out_size) {
    const float* w        = (const float*)d_in[0];
    const float* s        = (const float*)d_in[1];
    const int*   edge_src = (const int*)d_in[2];
    const int*   edge_dst = (const int*)d_in[3];
    const float* Wfc      = (const float*)d_in[4];
    const float* a_src    = (const float*)d_in[5];
    const float* a_dst    = (const float*)d_in[6];
    const float* W1       = (const float*)d_in[7];
    const float* b1       = (const float*)d_in[8];
    const float* W2       = (const float*)d_in[9];
    const float* b2       = (const float*)d_in[10];
    const float* gamma    = (const float*)d_in[11];
    const float* beta     = (const float*)d_in[12];
    float* out = (float*)d_out;

    const int NW = in_sizes[0] / 128;
    const int NS = in_sizes[1] / 128;
    const int E  = in_sizes[2];

    float* p_Wmat  = sym_addr<float>(g_Wmat);
    float* p_vsrc  = sym_addr<float>(g_vsrc);
    float* p_vdst  = sym_addr<float>(g_vdst);
    float* p_zw    = sym_addr<float>(g_zw);
    float* p_esrc  = sym_addr<float>(g_esrc);
    float* p_edst  = sym_addr<float>(g_edst);
    float* p_xn    = sym_addr<float>(g_xn);
    float* p_inter = sym_addr<float>(g_inter);
    float* p_hbuf  = sym_addr<float>(g_hbuf);

    // 1. tiny prep: Wmat, v_src, v_dst
    prep_kernel<<<64, 256>>>(Wfc, a_src, a_dst);

    // 2. z_w = w @ Wmat   (100000 x 128 x 128)
    sgemm_kernel<false, false, false>
        <<<dim3(1, (NW + 127) / 128), 256>>>(w, p_Wmat, nullptr, nullptr,
                                             p_zw, NW, 128, 128);

    // 3. e_src = w @ v_src,  e_dst = s @ v_dst
    proj_e_kernel<<<(NW + 7) / 8, 256>>>(w, p_vsrc, p_esrc, NW);
    proj_e_kernel<<<(NS + 7) / 8, 256>>>(s, p_vdst, p_edst, NS);

    // 4. CSR build (dst-bucketed edge list)
    zero_cnt_kernel<<<(NS + 255) / 256, 256>>>(NS);
    hist_kernel<<<1024, 256>>>(edge_dst, E);
    scan_kernel<<<1, 1024>>>(NS);
    scatter_kernel<<<1024, 256>>>(edge_src, edge_dst, E);

    // 5. segment softmax + message aggregation + elu + residual
    agg_kernel<<<(NS + 7) / 8, 256>>>(s, NS);

    // 6. LayerNorm
    ln_kernel<<<(NS + 7) / 8, 256>>>(gamma, beta, NS);

    // 7. FFN: inter = gelu(xn @ W1 + b1);  out = inter @ W2 + b2 + hbuf
    sgemm_kernel<true, true, false>
        <<<dim3(4, (NS + 127) / 128), 256>>>(p_xn, W1, b1, nullptr,
                                             p_inter, NS, 512, 128);
    sgemm_kernel<false, true, true>
        <<<dim3(1, (NS + 127) / 128), 256>>>(p_inter, W2, b2, p_hbuf,
                                             out, NS, 128, 512);
}

// round 5
// speedup vs baseline: 1.7827x; 1.7827x over previous
#include <cuda_runtime.h>
#include <math.h>

#define NW_MAX 100000
#define NS_MAX 25000
#define E_MAX  1600000

// ---------------------------------------------------------------------------
// Scratch (__device__ globals; no allocation allowed)
// ---------------------------------------------------------------------------
__device__ float g_Wmat[128 * 128];          // [i][h*16+d]
__device__ float g_vsrc[128 * 8];            // [i][h]
__device__ float g_vdst[128 * 8];            // [i][h]
__device__ float g_zw[(size_t)NW_MAX * 128]; // projected word feats
__device__ float g_esrc[NW_MAX * 8];
__device__ float g_edst[NS_MAX * 8];
__device__ int   g_cnt[NS_MAX];
__device__ int   g_off[NS_MAX + 1];
__device__ int   g_cur[NS_MAX];
__device__ int   g_csr[E_MAX];               // src indices bucketed by dst
__device__ float g_hbuf[NS_MAX * 128];       // elu(out)+s (pre-LN residual)
__device__ float g_xn[NS_MAX * 128];         // layernormed
__device__ float g_inter[(size_t)NS_MAX * 512];

__device__ __forceinline__ float gelu_exact(float x) {
    return 0.5f * x * (1.0f + erff(x * 0.70710678118654752f));
}

// ---------------------------------------------------------------------------
// Prep: Wmat[i][h*16+d] = Wfc[h,i,d]; v_src/v_dst[i][h] = sum_d Wfc[h,i,d]*a[h,d]
// ---------------------------------------------------------------------------
__global__ void prep_kernel(const float* __restrict__ Wfc,
                            const float* __restrict__ a_src,
                            const float* __restrict__ a_dst) {
    int idx = blockIdx.x * blockDim.x + threadIdx.x;
    if (idx < 128 * 128) {
        int i = idx >> 7;
        int hd = idx & 127;
        int h = hd >> 4, d = hd & 15;
        g_Wmat[i * 128 + hd] = Wfc[h * 2048 + i * 16 + d];
    }
    if (idx < 128 * 8) {
        int i = idx >> 3;
        int h = idx & 7;
        float s1 = 0.f, s2 = 0.f;
#pragma unroll
        for (int d = 0; d < 16; d++) {
            float wv = Wfc[h * 2048 + i * 16 + d];
            s1 = fmaf(wv, a_src[h * 16 + d], s1);
            s2 = fmaf(wv, a_dst[h * 16 + d], s2);
        }
        g_vsrc[i * 8 + h] = s1;
        g_vdst[i * 8 + h] = s2;
    }
}

// ---------------------------------------------------------------------------
// Tiled fp32 SGEMM: C[M,N] = act(A[M,K] @ B[K,N] + bias) + res
// 128x128 block tile, BK=8, 256 threads, 8x8 per-thread microtile.
// (identical to the Round-2 passing version)
// ---------------------------------------------------------------------------
template <bool GELU, bool BIAS, bool RES>
__global__ __launch_bounds__(256) void sgemm_kernel(
    const float* __restrict__ A, const float* __restrict__ B,
    const float* __restrict__ bias, const float* __restrict__ res,
    float* __restrict__ C, int M, int N, int K) {
    __shared__ float As[8][128];
    __shared__ float Bs[8][128];
    const int tid = threadIdx.x;
    const int tx = tid & 15;        // 16 col groups
    const int ty = tid >> 4;        // 16 row groups
    const int rowBase = blockIdx.y * 128;
    const int colBase = blockIdx.x * 128;

    float acc[8][8];
#pragma unroll
    for (int i = 0; i < 8; i++)
#pragma unroll
        for (int j = 0; j < 8; j++) acc[i][j] = 0.f;

    const int arow = tid >> 1, acol = (tid & 1) << 2;   // A: 128 rows x 8 k
    const int brow = tid >> 5, bcol = (tid & 31) << 2;  // B: 8 k x 128 cols
    const bool aval = (rowBase + arow) < M;
    const float* Aptr = A + (size_t)(rowBase + arow) * K + acol;
    const float* Bptr = B + (size_t)brow * N + colBase + bcol;

    for (int k0 = 0; k0 < K; k0 += 8) {
        float4 av = aval ? *(const float4*)(Aptr + k0)
                         : make_float4(0.f, 0.f, 0.f, 0.f);
        float4 bv = *(const float4*)(Bptr + (size_t)k0 * N);
        As[acol + 0][arow] = av.x;
        As[acol + 1][arow] = av.y;
        As[acol + 2][arow] = av.z;
        As[acol + 3][arow] = av.w;
        *(float4*)&Bs[brow][bcol] = bv;
        __syncthreads();
#pragma unroll
        for (int kk = 0; kk < 8; kk++) {
            float4 a0 = *(const float4*)&As[kk][ty * 8];
            float4 a1 = *(const float4*)&As[kk][ty * 8 + 4];
            float4 b0 = *(const float4*)&Bs[kk][tx * 8];
            float4 b1 = *(const float4*)&Bs[kk][tx * 8 + 4];
            float ar[8] = {a0.x, a0.y, a0.z, a0.w, a1.x, a1.y, a1.z, a1.w};
            float br[8] = {b0.x, b0.y, b0.z, b0.w, b1.x, b1.y, b1.z, b1.w};
#pragma unroll
            for (int i = 0; i < 8; i++)
#pragma unroll
                for (int j = 0; j < 8; j++)
                    acc[i][j] = fmaf(ar[i], br[j], acc[i][j]);
        }
        __syncthreads();
    }

#pragma unroll
    for (int i = 0; i < 8; i++) {
        int row = rowBase + ty * 8 + i;
        if (row >= M) continue;
#pragma unroll
        for (int j4 = 0; j4 < 8; j4 += 4) {
            int col = colBase + tx * 8 + j4;
            float v0 = acc[i][j4 + 0], v1 = acc[i][j4 + 1];
            float v2 = acc[i][j4 + 2], v3 = acc[i][j4 + 3];
            if (BIAS) {
                float4 bb = *(const float4*)(bias + col);
                v0 += bb.x; v1 += bb.y; v2 += bb.z; v3 += bb.w;
            }
            if (GELU) {
                v0 = gelu_exact(v0); v1 = gelu_exact(v1);
                v2 = gelu_exact(v2); v3 = gelu_exact(v3);
            }
            if (RES) {
                float4 rr = *(const float4*)(res + (size_t)row * N + col);
                v0 += rr.x; v1 += rr.y; v2 += rr.z; v3 += rr.w;
            }
            float4 ov = make_float4(v0, v1, v2, v3);
            *(float4*)(C + (size_t)row * N + col) = ov;
        }
    }
}

// ---------------------------------------------------------------------------
// ev: out[row*8+h] = sum_i X[row,i] * vmat[i,h]. Lane-per-(row,head):
// 4 rows per warp, 32 rows per block. vmat staged in smem (broadcast,
// conflict-free). Replaces the L1-thrashing proj_e.
// ---------------------------------------------------------------------------
__global__ __launch_bounds__(256) void ev_kernel(const float* __restrict__ X,
                                                 const float* __restrict__ vmat,
                                                 float* __restrict__ out,
                                                 int n) {
    __shared__ float vs[1024];
    int t = threadIdx.x;
    for (int i = t; i < 1024; i += 256) vs[i] = vmat[i];
    __syncthreads();
    int warp = t >> 5, lane = t & 31;
    int row = blockIdx.x * 32 + warp * 4 + (lane >> 3);
    int h = lane & 7;
    if (row >= n) return;
    const float4* xp = (const float4*)(X + (size_t)row * 128);
    float acc = 0.f;
#pragma unroll
    for (int c = 0; c < 32; c++) {
        float4 xv = xp[c];
        acc = fmaf(xv.x, vs[(c * 4 + 0) * 8 + h], acc);
        acc = fmaf(xv.y, vs[(c * 4 + 1) * 8 + h], acc);
        acc = fmaf(xv.z, vs[(c * 4 + 2) * 8 + h], acc);
        acc = fmaf(xv.w, vs[(c * 4 + 3) * 8 + h], acc);
    }
    out[row * 8 + h] = acc;
}

// ---------------------------------------------------------------------------
// CSR build
// ---------------------------------------------------------------------------
__global__ void zero_cnt_kernel(int ns) {
    int i = blockIdx.x * blockDim.x + threadIdx.x;
    if (i < ns) g_cnt[i] = 0;
}

__global__ void hist_kernel(const int* __restrict__ edst, int E) {
    for (int e = blockIdx.x * blockDim.x + threadIdx.x; e < E;
         e += gridDim.x * blockDim.x)
        atomicAdd(&g_cnt[edst[e]], 1);
}

__global__ void scan_kernel(int ns) {
    __shared__ int ssum[1024];
    int t = threadIdx.x;
    int per = (ns + 1023) >> 10;
    int base = t * per;
    int sum = 0;
    for (int i = 0; i < per; i++) {
        int idx = base + i;
        if (idx < ns) sum += g_cnt[idx];
    }
    ssum[t] = sum;
    __syncthreads();
    for (int off = 1; off < 1024; off <<= 1) {
        int v = (t >= off) ? ssum[t - off] : 0;
        __syncthreads();
        ssum[t] += v;
        __syncthreads();
    }
    int run = (t == 0) ? 0 : ssum[t - 1];
    for (int i = 0; i < per; i++) {
        int idx = base + i;
        if (idx < ns) {
            g_off[idx] = run;
            g_cur[idx] = run;
            run += g_cnt[idx];
        }
    }
    if (t == 1023) g_off[ns] = ssum[1023];
}

__global__ void scatter_kernel(const int* __restrict__ esrc_idx,
                               const int* __restrict__ edst_idx, int E) {
    for (int e = blockIdx.x * blockDim.x + threadIdx.x; e < E;
         e += gridDim.x * blockDim.x) {
        int dst = edst_idx[e];
        int pos = atomicAdd(&g_cur[dst], 1);
        g_csr[pos] = esrc_idx[e];
    }
}

// ---------------------------------------------------------------------------
// Aggregation: warp per dst node, two-pass segment softmax in registers.
// Lane l owns output cols [4l,4l+4) (head = l/4).
// ---------------------------------------------------------------------------
__global__ void agg_kernel(const float* __restrict__ s, int ns) {
    int dst = (blockIdx.x * blockDim.x + threadIdx.x) >> 5;
    if (dst >= ns) return;
    int lane = threadIdx.x & 31;
    int h = lane >> 2;
    float ed = g_edst[dst * 8 + h];
    int beg = g_off[dst], end = g_off[dst + 1];

    float m = -1e30f;
    for (int e = beg; e < end; ++e) {
        int src = g_csr[e];
        float sc = g_esrc[src * 8 + h] + ed;
        sc = sc > 0.f ? sc : 0.01f * sc;
        m = fmaxf(m, sc);
    }

    float d = 0.f, ax = 0.f, ay = 0.f, az = 0.f, aw = 0.f;
    for (int e = beg; e < end; ++e) {
        int src = g_csr[e];
        float sc = g_esrc[src * 8 + h] + ed;
        sc = sc > 0.f ? sc : 0.01f * sc;
        float p = __expf(sc - m);
        d += p;
        float4 z = *(const float4*)(g_zw + (size_t)src * 128 + lane * 4);
        ax = fmaf(p, z.x, ax); ay = fmaf(p, z.y, ay);
        az = fmaf(p, z.z, az); aw = fmaf(p, z.w, aw);
    }
    float inv = 1.f / fmaxf(d, 1e-9f);
    float4 sv = *(const float4*)(s + (size_t)dst * 128 + lane * 4);
    float o0 = ax * inv, o1 = ay * inv, o2 = az * inv, o3 = aw * inv;
    o0 = o0 > 0.f ? o0 : (__expf(o0) - 1.f);
    o1 = o1 > 0.f ? o1 : (__expf(o1) - 1.f);
    o2 = o2 > 0.f ? o2 : (__expf(o2) - 1.f);
    o3 = o3 > 0.f ? o3 : (__expf(o3) - 1.f);
    *(float4*)(g_hbuf + (size_t)dst * 128 + lane * 4) =
        make_float4(o0 + sv.x, o1 + sv.y, o2 + sv.z, o3 + sv.w);
}

// ---------------------------------------------------------------------------
// LayerNorm: one warp per row, population variance, eps=1e-6
// ---------------------------------------------------------------------------
__global__ void ln_kernel(const float* __restrict__ gamma,
                          const float* __restrict__ beta, int ns) {
    int row = (blockIdx.x * blockDim.x + threadIdx.x) >> 5;
    if (row >= ns) return;
    int lane = threadIdx.x & 31;
    float4 v = *(const float4*)(g_hbuf + (size_t)row * 128 + lane * 4);
    float sum = v.x + v.y + v.z + v.w;
    float sq = v.x * v.x + v.y * v.y + v.z * v.z + v.w * v.w;
#pragma unroll
    for (int o = 16; o; o >>= 1) {
        sum += __shfl_xor_sync(0xffffffffu, sum, o);
        sq += __shfl_xor_sync(0xffffffffu, sq, o);
    }
    float mean = sum * (1.f / 128.f);
    float var = sq * (1.f / 128.f) - mean * mean;
    float inv = rsqrtf(var + 1e-6f);
    float4 g = *(const float4*)(gamma + lane * 4);
    float4 b = *(const float4*)(beta + lane * 4);
    float4 o4;
    o4.x = (v.x - mean) * inv * g.x + b.x;
    o4.y = (v.y - mean) * inv * g.y + b.y;
    o4.z = (v.z - mean) * inv * g.z + b.z;
    o4.w = (v.w - mean) * inv * g.w + b.w;
    *(float4*)(g_xn + (size_t)row * 128 + lane * 4) = o4;
}

// ---------------------------------------------------------------------------
// Host launcher
// ---------------------------------------------------------------------------
template <typename T>
static T* sym_addr(const void* symbol) {
    void* p = nullptr;
    cudaGetSymbolAddress(&p, symbol);
    return (T*)p;
}

extern "C" void kernel_launch(void* const* d_in, const int* in_sizes, int n_in,
                              void* d_out, int out_size) {
    const float* w        = (const float*)d_in[0];
    const float* s        = (const float*)d_in[1];
    const int*   edge_src = (const int*)d_in[2];
    const int*   edge_dst = (const int*)d_in[3];
    const float* Wfc      = (const float*)d_in[4];
    const float* a_src    = (const float*)d_in[5];
    const float* a_dst    = (const float*)d_in[6];
    const float* W1       = (const float*)d_in[7];
    const float* b1       = (const float*)d_in[8];
    const float* W2       = (const float*)d_in[9];
    const float* b2       = (const float*)d_in[10];
    const float* gamma    = (const float*)d_in[11];
    const float* beta     = (const float*)d_in[12];
    float* out = (float*)d_out;

    const int NW = in_sizes[0] / 128;
    const int NS = in_sizes[1] / 128;
    const int E  = in_sizes[2];

    float* p_Wmat  = sym_addr<float>(g_Wmat);
    float* p_vsrc  = sym_addr<float>(g_vsrc);
    float* p_vdst  = sym_addr<float>(g_vdst);
    float* p_zw    = sym_addr<float>(g_zw);
    float* p_esrc  = sym_addr<float>(g_esrc);
    float* p_edst  = sym_addr<float>(g_edst);
    float* p_xn    = sym_addr<float>(g_xn);
    float* p_inter = sym_addr<float>(g_inter);
    float* p_hbuf  = sym_addr<float>(g_hbuf);

    // 1. prep: Wmat (transposed Wfc), v_src, v_dst
    prep_kernel<<<64, 256>>>(Wfc, a_src, a_dst);

    // 2. z_w = w @ Wmat   (100000 x 128 x 128)
    sgemm_kernel<false, false, false>
        <<<dim3(1, (NW + 127) / 128), 256>>>(w, p_Wmat, nullptr, nullptr,
                                             p_zw, NW, 128, 128);

    // 3. e_src = w @ v_src,  e_dst = s @ v_dst  (lane-per-(row,h))
    ev_kernel<<<(NW + 31) / 32, 256>>>(w, p_vsrc, p_esrc, NW);
    ev_kernel<<<(NS + 31) / 32, 256>>>(s, p_vdst, p_edst, NS);

    // 4. CSR build
    zero_cnt_kernel<<<(NS + 255) / 256, 256>>>(NS);
    hist_kernel<<<1024, 256>>>(edge_dst, E);
    scan_kernel<<<1, 1024>>>(NS);
    scatter_kernel<<<1024, 256>>>(edge_src, edge_dst, E);

    // 5. segment softmax + aggregation + elu + residual
    agg_kernel<<<(NS + 7) / 8, 256>>>(s, NS);

    // 6. LayerNorm
    ln_kernel<<<(NS + 7) / 8, 256>>>(gamma, beta, NS);

    // 7. FFN
    sgemm_kernel<true, true, false>
        <<<dim3(4, (NS + 127) / 128), 256>>>(p_xn, W1, b1, nullptr,
                                             p_inter, NS, 512, 128);
    sgemm_kernel<false, true, true>
        <<<dim3(1, (NS + 127) / 128), 256>>>(p_inter, W2, b2, p_hbuf,
                                             out, NS, 128, 512);
}